// round 6
// baseline (speedup 1.0000x reference)
#include <cuda_runtime.h>
#include <cuda_bf16.h>
#include <cstdint>

// flows:  [B=4, L=32, 2,  H=128, W=128] fp32 planar input
// images: [B=4, L=32, 16, H=128, W=128] fp32 planar input/output
// Internal state is channel-interleaved: images [bt][hw][16], flows [bt][hw][2].
// pscan doubling steps s = 1,2,4,8,16 with no-copy routing:
//   step s: t in [s,2s)  -> FINAL: dual-write planar d_out + interleaved iF
//           t in [2s,L)  -> scratch (interleaved ping-pong)
//   reads j = t-s: j==0 -> planar input, 1<=j<s -> iF, j>=s -> prev scratch.

constexpr int B  = 4;
constexpr int L  = 32;
constexpr int C  = 16;
constexpr int H  = 128;
constexpr int W  = 128;
constexpr int HW = H * W;
constexpr int FSTR = 2 * HW;
constexpr int ISTR = C * HW;

__device__ float g_iF [B * L * ISTR];  // interleaved image finals
__device__ float g_iS0[B * L * ISTR];  // ping
__device__ float g_iS1[B * L * ISTR];  // pong
__device__ float g_fIn[B * L * FSTR];  // interleaved input flows
__device__ float g_fF [B * L * FSTR];  // flow finals
__device__ float g_fS0[B * L * FSTR];
__device__ float g_fS1[B * L * FSTR];

struct GridS {
    int o00, o01, o10, o11;
    float w00, w01, w10, w11;   // border-pad weights (flows)
    float z00, z01, z10, z11;   // zeros-pad weights (images)
};

// EXACT reference-formula sequence (normalized coords, fmod wrap, unnormalize).
// Do NOT reassociate: the wrap is discontinuous, rounding-sensitive.
__device__ __forceinline__ GridS make_grid(float fx, float fyv, int w, int h)
{
    GridS g;
    float gx = ((float)w + 0.5f) * (2.0f / W) - 1.0f + fx;
    float gy = ((float)h + 0.5f) * (2.0f / H) - 1.0f + fyv;

    float r = fmodf(gx + 1.0f, 2.0f);
    if (r < 0.0f) r += 2.0f;
    float gxw = r - 1.0f;

    float x  = (gxw + 1.0f) * (0.5f * W) - 0.5f;
    float yy = (gy  + 1.0f) * (0.5f * H) - 0.5f;

    float x0f = floorf(x);
    float y0f = floorf(yy);
    float wx = x - x0f;
    float wy = yy - y0f;
    int x0 = (int)x0f, y0 = (int)y0f;
    int x1 = x0 + 1,   y1 = y0 + 1;

    int x0c = min(max(x0, 0), W - 1);
    int x1c = min(max(x1, 0), W - 1);
    int y0c = min(max(y0, 0), H - 1);
    int y1c = min(max(y1, 0), H - 1);

    g.w00 = (1.0f - wx) * (1.0f - wy);
    g.w01 = wx * (1.0f - wy);
    g.w10 = (1.0f - wx) * wy;
    g.w11 = wx * wy;

    g.o00 = y0c * W + x0c;
    g.o01 = y0c * W + x1c;
    g.o10 = y1c * W + x0c;
    g.o11 = y1c * W + x1c;

    bool vx0 = (x0 >= 0) && (x0 < W);
    bool vx1 = (x1 >= 0) && (x1 < W);
    bool vy0 = (y0 >= 0) && (y0 < H);
    bool vy1 = (y1 >= 0) && (y1 < H);
    g.z00 = (vy0 && vx0) ? g.w00 : 0.0f;
    g.z01 = (vy0 && vx1) ? g.w01 : 0.0f;
    g.z10 = (vy1 && vx0) ? g.w10 : 0.0f;
    g.z11 = (vy1 && vx1) ? g.w11 : 0.0f;
    return g;
}

// ---- flows: planar -> interleaved ------------------------------------------
__global__ __launch_bounds__(256)
void flow_pre_kernel(const float* __restrict__ src, float* __restrict__ dst)
{
    int p = blockIdx.x * 256 + threadIdx.x;
    size_t bt = blockIdx.y;
    const float* s = src + bt * FSTR;
    ((float2*)(dst + bt * FSTR))[p] = make_float2(s[p], s[HW + p]);
}

// ---- t=0 image passthrough: planar input -> planar d_out --------------------
__global__ __launch_bounds__(256)
void t0_copy_kernel(const float* __restrict__ src, float* __restrict__ dst)
{
    int idx = blockIdx.x * 256 + threadIdx.x;          // gridDim.x = 256
    size_t off = (size_t)blockIdx.y * L * ISTR;        // b slice, t = 0
    ((float4*)(dst + off))[idx] = ((const float4*)(src + off))[idx];
}

// ---- step 1: planar sources, 1 thread/pixel/16ch ----------------------------
__global__ __launch_bounds__(256)
void step1_kernel(const float* __restrict__ img,
                  const float* __restrict__ fIn,
                  float* __restrict__ out,
                  float* __restrict__ iF,
                  float* __restrict__ iS,
                  float* __restrict__ fF,
                  float* __restrict__ fS)
{
    __shared__ float sm[256 * 17];
    int tid = threadIdx.x;
    int pb = blockIdx.x * 256;                     // gridDim.x = 64
    int p = pb + tid;
    int y = blockIdx.y;                            // B*31
    int b = y / 31, trel = y % 31;
    int t = trel + 1, j = trel;
    size_t bt  = (size_t)(b * L + t);
    size_t btj = (size_t)(b * L + j);

    float2 fc = ((const float2*)(fIn + bt * FSTR))[p];
    int w = p & (W - 1), h = p >> 7;
    GridS g = make_grid(fc.x, fc.y, w, h);

    // flow update (src = input flows)
    {
        const float2* fsrc = (const float2*)(fIn + btj * FSTR);
        float2 t00 = fsrc[g.o00], t01 = fsrc[g.o01];
        float2 t10 = fsrc[g.o10], t11 = fsrc[g.o11];
        float nx = fc.x + g.w00 * t00.x + g.w01 * t01.x + g.w10 * t10.x + g.w11 * t11.x;
        float ny = fc.y + g.w00 * t00.y + g.w01 * t01.y + g.w10 * t10.y + g.w11 * t11.y;
        float* fdst = (t == 1) ? fF : fS;
        ((float2*)(fdst + bt * FSTR))[p] = make_float2(nx, ny);
    }

    const float* cur  = img + bt  * ISTR + p;
    const float* srcb = img + btj * ISTR;
    float acc[16];
    #pragma unroll
    for (int c = 0; c < 16; c++) {
        const float* q = srcb + c * HW;
        acc[c] = cur[c * HW] + g.z00 * q[g.o00] + g.z01 * q[g.o01]
                             + g.z10 * q[g.o10] + g.z11 * q[g.o11];
    }

    if (t == 1) {   // final: planar d_out directly (coalesced)
        float* d = out + bt * ISTR + p;
        #pragma unroll
        for (int c = 0; c < 16; c++) d[c * HW] = acc[c];
    }

    // interleaved store (finals -> iF, rest -> scratch) via smem bounce
    #pragma unroll
    for (int c = 0; c < 16; c++) sm[tid * 17 + c] = acc[c];
    __syncthreads();
    float* dd = ((t == 1) ? iF : iS) + bt * ISTR + (size_t)pb * 16;
    #pragma unroll
    for (int k = 0; k < 16; k++) {
        int idx = tid + k * 256;
        dd[idx] = sm[(idx >> 4) * 17 + (idx & 15)];
    }
}

// ---- final-region step (s>=2): dual store planar + interleaved --------------
__global__ __launch_bounds__(256)
void stepF_kernel(const float* __restrict__ img,
                  const float* iFr, float* iFw,
                  const float* __restrict__ iprev,
                  float* __restrict__ out,
                  const float* __restrict__ fIn,
                  const float* fF_r, float* fF_w,
                  const float* __restrict__ fprev,
                  int s, int do_flow)
{
    __shared__ float sm[64 * 17];
    int tid = threadIdx.x;
    int chunk = tid & 3;
    int pl = tid >> 2;
    int pb = blockIdx.x * 64, p = pb + pl;         // gridDim.x = 256
    int y = blockIdx.y;                            // B*s
    int b = y / s, trel = y % s;
    int t = s + trel, j = trel;
    size_t bt  = (size_t)(b * L + t);
    size_t btj = (size_t)(b * L + j);

    float2 fc = ((const float2*)(fprev + bt * FSTR))[p];
    int w = p & (W - 1), h = p >> 7;
    GridS g = make_grid(fc.x, fc.y, w, h);

    float4 cv = *(const float4*)(iprev + bt * ISTR + (size_t)p * 16 + chunk * 4);
    float a0 = cv.x, a1 = cv.y, a2 = cv.z, a3 = cv.w;

    if (j == 0) {
        const float* base = img + btj * ISTR + (chunk * 4) * HW;
        #pragma unroll
        for (int cc = 0; cc < 4; cc++) {
            const float* q = base + cc * HW;
            float v = g.z00 * q[g.o00] + g.z01 * q[g.o01]
                    + g.z10 * q[g.o10] + g.z11 * q[g.o11];
            if (cc == 0) a0 += v; else if (cc == 1) a1 += v;
            else if (cc == 2) a2 += v; else a3 += v;
        }
    } else {
        const float* srcp = iFr + btj * ISTR + chunk * 4;
        float4 v00 = *(const float4*)(srcp + (size_t)g.o00 * 16);
        float4 v01 = *(const float4*)(srcp + (size_t)g.o01 * 16);
        float4 v10 = *(const float4*)(srcp + (size_t)g.o10 * 16);
        float4 v11 = *(const float4*)(srcp + (size_t)g.o11 * 16);
        a0 += g.z00 * v00.x + g.z01 * v01.x + g.z10 * v10.x + g.z11 * v11.x;
        a1 += g.z00 * v00.y + g.z01 * v01.y + g.z10 * v10.y + g.z11 * v11.y;
        a2 += g.z00 * v00.z + g.z01 * v01.z + g.z10 * v10.z + g.z11 * v11.z;
        a3 += g.z00 * v00.w + g.z01 * v01.w + g.z10 * v10.w + g.z11 * v11.w;
    }

    *(float4*)(iFw + bt * ISTR + (size_t)p * 16 + chunk * 4) =
        make_float4(a0, a1, a2, a3);

    int cb = chunk * 4;
    sm[pl * 17 + cb + 0] = a0;
    sm[pl * 17 + cb + 1] = a1;
    sm[pl * 17 + cb + 2] = a2;
    sm[pl * 17 + cb + 3] = a3;
    __syncthreads();
    float* dst = out + bt * ISTR;
    #pragma unroll
    for (int rr = 0; rr < 4; rr++) {
        int c = (tid >> 6) + rr * 4;
        int i = tid & 63;
        dst[c * HW + pb + i] = sm[i * 17 + c];
    }

    if (do_flow && chunk == 0) {
        const float* fbase = (j == 0) ? fIn : fF_r;
        const float2* fsrc = (const float2*)(fbase + btj * FSTR);
        float2 t00 = fsrc[g.o00], t01 = fsrc[g.o01];
        float2 t10 = fsrc[g.o10], t11 = fsrc[g.o11];
        float nx = fc.x + g.w00 * t00.x + g.w01 * t01.x + g.w10 * t10.x + g.w11 * t11.x;
        float ny = fc.y + g.w00 * t00.y + g.w01 * t01.y + g.w10 * t10.y + g.w11 * t11.y;
        ((float2*)(fF_w + bt * FSTR))[p] = make_float2(nx, ny);
    }
}

// ---- scratch-region step (s>=2): lean, all interleaved ----------------------
__global__ __launch_bounds__(256)
void stepS_kernel(const float* __restrict__ iprev, float* __restrict__ iscr,
                  const float* __restrict__ fprev, float* __restrict__ fscr,
                  int s, int Ls, int do_flow)
{
    int tid = threadIdx.x;
    int chunk = tid & 3;
    int pl = tid >> 2;
    int p = blockIdx.x * 64 + pl;                  // gridDim.x = 256
    int y = blockIdx.y;                            // B*Ls, Ls = L-2s
    int b = y / Ls, trel = y % Ls;
    int t = 2 * s + trel;
    size_t bt  = (size_t)(b * L + t);
    size_t btj = (size_t)(b * L + t - s);

    float2 fc = ((const float2*)(fprev + bt * FSTR))[p];
    int w = p & (W - 1), h = p >> 7;
    GridS g = make_grid(fc.x, fc.y, w, h);

    float4 cv = *(const float4*)(iprev + bt * ISTR + (size_t)p * 16 + chunk * 4);
    const float* srcp = iprev + btj * ISTR + chunk * 4;
    float4 v00 = *(const float4*)(srcp + (size_t)g.o00 * 16);
    float4 v01 = *(const float4*)(srcp + (size_t)g.o01 * 16);
    float4 v10 = *(const float4*)(srcp + (size_t)g.o10 * 16);
    float4 v11 = *(const float4*)(srcp + (size_t)g.o11 * 16);
    float a0 = cv.x + g.z00 * v00.x + g.z01 * v01.x + g.z10 * v10.x + g.z11 * v11.x;
    float a1 = cv.y + g.z00 * v00.y + g.z01 * v01.y + g.z10 * v10.y + g.z11 * v11.y;
    float a2 = cv.z + g.z00 * v00.z + g.z01 * v01.z + g.z10 * v10.z + g.z11 * v11.z;
    float a3 = cv.w + g.z00 * v00.w + g.z01 * v01.w + g.z10 * v10.w + g.z11 * v11.w;

    *(float4*)(iscr + bt * ISTR + (size_t)p * 16 + chunk * 4) =
        make_float4(a0, a1, a2, a3);

    if (do_flow && chunk == 0) {
        const float2* fsrc = (const float2*)(fprev + btj * FSTR);
        float2 t00 = fsrc[g.o00], t01 = fsrc[g.o01];
        float2 t10 = fsrc[g.o10], t11 = fsrc[g.o11];
        float nx = fc.x + g.w00 * t00.x + g.w01 * t01.x + g.w10 * t10.x + g.w11 * t11.x;
        float ny = fc.y + g.w00 * t00.y + g.w01 * t01.y + g.w10 * t10.y + g.w11 * t11.y;
        ((float2*)(fscr + bt * FSTR))[p] = make_float2(nx, ny);
    }
}

extern "C" void kernel_launch(void* const* d_in, const int* in_sizes, int n_in,
                              void* d_out, int out_size)
{
    const float* flows  = (const float*)d_in[0];
    const float* images = (const float*)d_in[1];
    if (n_in >= 2 && in_sizes[0] > in_sizes[1]) {
        flows  = (const float*)d_in[1];
        images = (const float*)d_in[0];
    }
    float* out = (float*)d_out;

    float *iF, *iS0, *iS1, *fIn, *fF, *fS0, *fS1;
    cudaGetSymbolAddress((void**)&iF,  g_iF);
    cudaGetSymbolAddress((void**)&iS0, g_iS0);
    cudaGetSymbolAddress((void**)&iS1, g_iS1);
    cudaGetSymbolAddress((void**)&fIn, g_fIn);
    cudaGetSymbolAddress((void**)&fF,  g_fF);
    cudaGetSymbolAddress((void**)&fS0, g_fS0);
    cudaGetSymbolAddress((void**)&fS1, g_fS1);

    flow_pre_kernel<<<dim3(64, B * L), 256>>>(flows, fIn);
    t0_copy_kernel <<<dim3(256, B),    256>>>(images, out);

    // s = 1
    step1_kernel<<<dim3(64, B * 31), 256>>>(images, fIn, out, iF, iS0, fF, fS0);

    // s = 2
    stepF_kernel<<<dim3(256, B * 2),  256>>>(images, iF, iF, iS0, out,
                                             fIn, fF, fF, fS0, 2, 1);
    stepS_kernel<<<dim3(256, B * 28), 256>>>(iS0, iS1, fS0, fS1, 2, 28, 1);

    // s = 4
    stepF_kernel<<<dim3(256, B * 4),  256>>>(images, iF, iF, iS1, out,
                                             fIn, fF, fF, fS1, 4, 1);
    stepS_kernel<<<dim3(256, B * 24), 256>>>(iS1, iS0, fS1, fS0, 4, 24, 1);

    // s = 8
    stepF_kernel<<<dim3(256, B * 8),  256>>>(images, iF, iF, iS0, out,
                                             fIn, fF, fF, fS0, 8, 1);
    stepS_kernel<<<dim3(256, B * 16), 256>>>(iS0, iS1, fS0, fS1, 8, 16, 1);

    // s = 16 (all final, no flow update)
    stepF_kernel<<<dim3(256, B * 16), 256>>>(images, iF, iF, iS1, out,
                                             fIn, fF, fF, fS1, 16, 0);
}

// round 7
// speedup vs baseline: 1.2721x; 1.2721x over previous
#include <cuda_runtime.h>
#include <cuda_bf16.h>
#include <cstdint>

// flows:  [B=4, L=32, 2,  H=128, W=128] fp32 planar input
// images: [B=4, L=32, 16, H=128, W=128] fp32 planar input/output
// Internal: channel-interleaved images [bt][hw][16], flows [bt][hw][2].
// pscan steps s = 1,2,4,8,16, no-copy routing:
//   step s: t in [s,2s) FINAL -> planar d_out (+ interleaved iF unless last step)
//           t in [2s,L)       -> interleaved scratch ping-pong
//   reads j = t-s: j==0 -> iIn, 1<=j<s -> iF, j>=s -> prev scratch.
// Flow finals fF[t] are only read at s=2,4 -> skip final flow writes at s>=4.

constexpr int B  = 4;
constexpr int L  = 32;
constexpr int C  = 16;
constexpr int H  = 128;
constexpr int W  = 128;
constexpr int HW = H * W;
constexpr int FSTR = 2 * HW;
constexpr int ISTR = C * HW;

__device__ float g_iIn[B * L * ISTR];  // interleaved input images
__device__ float g_iF [B * L * ISTR];  // interleaved finals
__device__ float g_iS0[B * L * ISTR];
__device__ float g_iS1[B * L * ISTR];
__device__ float g_fIn[B * L * FSTR];
__device__ float g_fF [B * L * FSTR];
__device__ float g_fS0[B * L * FSTR];
__device__ float g_fS1[B * L * FSTR];

struct GridS {
    int o00, o01, o10, o11;
    float w00, w01, w10, w11;   // border-pad weights (flows)
    float z00, z01, z10, z11;   // zeros-pad weights (images)
};

// EXACT reference-formula sequence (normalized coords, fmod wrap, unnormalize).
// Do NOT reassociate: the x-wrap is discontinuous and rounding-sensitive.
__device__ __forceinline__ GridS make_grid(float fx, float fyv, int w, int h)
{
    GridS g;
    float gx = ((float)w + 0.5f) * (2.0f / W) - 1.0f + fx;
    float gy = ((float)h + 0.5f) * (2.0f / H) - 1.0f + fyv;

    float r = fmodf(gx + 1.0f, 2.0f);
    if (r < 0.0f) r += 2.0f;
    float gxw = r - 1.0f;

    float x  = (gxw + 1.0f) * (0.5f * W) - 0.5f;
    float yy = (gy  + 1.0f) * (0.5f * H) - 0.5f;

    float x0f = floorf(x);
    float y0f = floorf(yy);
    float wx = x - x0f;
    float wy = yy - y0f;
    int x0 = (int)x0f, y0 = (int)y0f;
    int x1 = x0 + 1,   y1 = y0 + 1;

    int x0c = min(max(x0, 0), W - 1);
    int x1c = min(max(x1, 0), W - 1);
    int y0c = min(max(y0, 0), H - 1);
    int y1c = min(max(y1, 0), H - 1);

    g.w00 = (1.0f - wx) * (1.0f - wy);
    g.w01 = wx * (1.0f - wy);
    g.w10 = (1.0f - wx) * wy;
    g.w11 = wx * wy;

    g.o00 = y0c * W + x0c;
    g.o01 = y0c * W + x1c;
    g.o10 = y1c * W + x0c;
    g.o11 = y1c * W + x1c;

    bool vx0 = (x0 >= 0) && (x0 < W);
    bool vx1 = (x1 >= 0) && (x1 < W);
    bool vy0 = (y0 >= 0) && (y0 < H);
    bool vy1 = (y1 >= 0) && (y1 < H);
    g.z00 = (vy0 && vx0) ? g.w00 : 0.0f;
    g.z01 = (vy0 && vx1) ? g.w01 : 0.0f;
    g.z10 = (vy1 && vx0) ? g.w10 : 0.0f;
    g.z11 = (vy1 && vx1) ? g.w11 : 0.0f;
    return g;
}

// ---- images: planar -> interleaved ------------------------------------------
__global__ __launch_bounds__(256)
void img_pre_kernel(const float* __restrict__ src, float* __restrict__ dst)
{
    __shared__ float sm[64 * 17];
    int tid = threadIdx.x;
    int pb = blockIdx.x * 64;
    size_t bt = blockIdx.y;
    const float* s = src + bt * ISTR;
    float* d = dst + bt * ISTR;
    #pragma unroll
    for (int rr = 0; rr < 4; rr++) {
        int c = (tid >> 6) + rr * 4;
        int i = tid & 63;
        sm[i * 17 + c] = s[c * HW + pb + i];
    }
    __syncthreads();
    #pragma unroll
    for (int k = 0; k < 4; k++) {
        int idx = tid + k * 256;
        d[(size_t)pb * 16 + idx] = sm[(idx >> 4) * 17 + (idx & 15)];
    }
}

// ---- flows: planar -> interleaved -------------------------------------------
__global__ __launch_bounds__(256)
void flow_pre_kernel(const float* __restrict__ src, float* __restrict__ dst)
{
    int p = blockIdx.x * 256 + threadIdx.x;
    size_t bt = blockIdx.y;
    const float* s = src + bt * FSTR;
    ((float2*)(dst + bt * FSTR))[p] = make_float2(s[p], s[HW + p]);
}

// ---- t=0 image passthrough: planar input -> planar d_out --------------------
__global__ __launch_bounds__(256)
void t0_copy_kernel(const float* __restrict__ src, float* __restrict__ dst)
{
    int idx = blockIdx.x * 256 + threadIdx.x;          // gridDim.x = 256
    size_t off = (size_t)blockIdx.y * L * ISTR;        // b slice, t = 0
    ((float4*)(dst + off))[idx] = ((const float4*)(src + off))[idx];
}

// ---- fused pscan step, templated --------------------------------------------
// FMODE: 1 = flow everywhere, 2 = flow only for scratch region, 0 = no flow.
template<int S, int FMODE>
__global__ __launch_bounds__(256)
void step_kernel(const float* __restrict__ iIn, const float* iFr, float* iFw,
                 const float* __restrict__ iprev, float* __restrict__ iscr,
                 float* __restrict__ out,
                 const float* __restrict__ fIn, const float* fFr, float* fFw,
                 const float* __restrict__ fprev, float* __restrict__ fscr)
{
    constexpr int Ls = L - S;
    constexpr bool LAST = (S == 16);
    __shared__ float sm[64 * 17];

    int tid = threadIdx.x;
    int chunk = tid & 3;
    int pl = tid >> 2;
    int pb = blockIdx.x * 64, p = pb + pl;         // gridDim.x = 256
    int y = blockIdx.y;                            // B * Ls
    int b = y / Ls, trel = y % Ls;
    int t = S + trel, j = trel;
    bool final_t = (trel < S);
    size_t bt  = (size_t)(b * L + t);
    size_t btj = (size_t)(b * L + j);

    float2 fc = ((const float2*)(fprev + bt * FSTR))[p];
    int w = p & (W - 1), h = p >> 7;
    GridS g = make_grid(fc.x, fc.y, w, h);

    // ---- image: interleaved gather, 4 channels/thread ----
    float4 cv = *(const float4*)(iprev + bt * ISTR + (size_t)p * 16 + chunk * 4);
    const float* ibase = (j == 0) ? iIn : (j < S) ? iFr : iprev;
    const float* srcp = ibase + btj * ISTR + chunk * 4;
    float4 v00 = *(const float4*)(srcp + (size_t)g.o00 * 16);
    float4 v01 = *(const float4*)(srcp + (size_t)g.o01 * 16);
    float4 v10 = *(const float4*)(srcp + (size_t)g.o10 * 16);
    float4 v11 = *(const float4*)(srcp + (size_t)g.o11 * 16);
    float a0 = cv.x + g.z00 * v00.x + g.z01 * v01.x + g.z10 * v10.x + g.z11 * v11.x;
    float a1 = cv.y + g.z00 * v00.y + g.z01 * v01.y + g.z10 * v10.y + g.z11 * v11.y;
    float a2 = cv.z + g.z00 * v00.z + g.z01 * v01.z + g.z10 * v10.z + g.z11 * v11.z;
    float a3 = cv.w + g.z00 * v00.w + g.z01 * v01.w + g.z10 * v10.w + g.z11 * v11.w;

    if (final_t) {
        if (!LAST) {   // later steps gather from iF; last step's finals never re-read
            *(float4*)(iFw + bt * ISTR + (size_t)p * 16 + chunk * 4) =
                make_float4(a0, a1, a2, a3);
        }
        // planar d_out via conflict-free smem bounce
        int cb = chunk * 4;
        sm[pl * 17 + cb + 0] = a0;
        sm[pl * 17 + cb + 1] = a1;
        sm[pl * 17 + cb + 2] = a2;
        sm[pl * 17 + cb + 3] = a3;
        __syncthreads();
        float* dst = out + bt * ISTR;
        #pragma unroll
        for (int rr = 0; rr < 4; rr++) {
            int c = (tid >> 6) + rr * 4;
            int i = tid & 63;
            dst[c * HW + pb + i] = sm[i * 17 + c];
        }
    } else {
        *(float4*)(iscr + bt * ISTR + (size_t)p * 16 + chunk * 4) =
            make_float4(a0, a1, a2, a3);
    }

    // ---- flow: chunk-0 lanes ----
    if (FMODE != 0 && chunk == 0) {
        bool doflow = (FMODE == 1) || !final_t;
        if (doflow) {
            const float* fbase = (j == 0) ? fIn : (j < S) ? fFr : fprev;
            const float2* fsrc = (const float2*)(fbase + btj * FSTR);
            float2 t00 = fsrc[g.o00], t01 = fsrc[g.o01];
            float2 t10 = fsrc[g.o10], t11 = fsrc[g.o11];
            float nx = fc.x + g.w00 * t00.x + g.w01 * t01.x + g.w10 * t10.x + g.w11 * t11.x;
            float ny = fc.y + g.w00 * t00.y + g.w01 * t01.y + g.w10 * t10.y + g.w11 * t11.y;
            float* fdst = final_t ? fFw : fscr;
            ((float2*)(fdst + bt * FSTR))[p] = make_float2(nx, ny);
        }
    }
}

extern "C" void kernel_launch(void* const* d_in, const int* in_sizes, int n_in,
                              void* d_out, int out_size)
{
    const float* flows  = (const float*)d_in[0];
    const float* images = (const float*)d_in[1];
    if (n_in >= 2 && in_sizes[0] > in_sizes[1]) {
        flows  = (const float*)d_in[1];
        images = (const float*)d_in[0];
    }
    float* out = (float*)d_out;

    float *iIn, *iF, *iS0, *iS1, *fIn, *fF, *fS0, *fS1;
    cudaGetSymbolAddress((void**)&iIn, g_iIn);
    cudaGetSymbolAddress((void**)&iF,  g_iF);
    cudaGetSymbolAddress((void**)&iS0, g_iS0);
    cudaGetSymbolAddress((void**)&iS1, g_iS1);
    cudaGetSymbolAddress((void**)&fIn, g_fIn);
    cudaGetSymbolAddress((void**)&fF,  g_fF);
    cudaGetSymbolAddress((void**)&fS0, g_fS0);
    cudaGetSymbolAddress((void**)&fS1, g_fS1);

    img_pre_kernel <<<dim3(256, B * L), 256>>>(images, iIn);
    flow_pre_kernel<<<dim3(64,  B * L), 256>>>(flows, fIn);
    t0_copy_kernel <<<dim3(256, B),     256>>>(images, out);

    step_kernel<1, 1><<<dim3(256, B * 31), 256>>>(iIn, iF, iF, iIn, iS0, out,
                                                  fIn, fF, fF, fIn, fS0);
    step_kernel<2, 1><<<dim3(256, B * 30), 256>>>(iIn, iF, iF, iS0, iS1, out,
                                                  fIn, fF, fF, fS0, fS1);
    step_kernel<4, 2><<<dim3(256, B * 28), 256>>>(iIn, iF, iF, iS1, iS0, out,
                                                  fIn, fF, fF, fS1, fS0);
    step_kernel<8, 2><<<dim3(256, B * 24), 256>>>(iIn, iF, iF, iS0, iS1, out,
                                                  fIn, fF, fF, fS0, fS1);
    step_kernel<16, 0><<<dim3(256, B * 16), 256>>>(iIn, iF, iF, iS1, iS0, out,
                                                   fIn, fF, fF, fS1, fS0);
}

// round 8
// speedup vs baseline: 1.5409x; 1.2113x over previous
#include <cuda_runtime.h>
#include <cuda_fp16.h>
#include <cstdint>

// flows:  [B=4, L=32, 2,  H=128, W=128] fp32 planar input (fp32 everywhere internally)
// images: [B=4, L=32, 16, H=128, W=128] fp32 planar in/out; internal state fp16
//         channel-interleaved [bt][hw][16].
// pscan steps s = 1,2,4,8,16, no-copy routing:
//   step s: t in [s,2s) FINAL -> planar fp32 d_out (+ fp16 iF unless last step)
//           t in [2s,L)       -> fp16 scratch ping-pong
//   reads j = t-s: j==0 -> iIn, 1<=j<s -> iF, j>=s -> prev scratch.
// Flow finals fF[t] only read at s=2,4 -> skip final flow writes at s>=4.

constexpr int B  = 4;
constexpr int L  = 32;
constexpr int C  = 16;
constexpr int H  = 128;
constexpr int W  = 128;
constexpr int HW = H * W;
constexpr int FSTR = 2 * HW;
constexpr int ISTR = C * HW;

__device__ __align__(16) __half g_iIn[B * L * ISTR];
__device__ __align__(16) __half g_iF [B * L * ISTR];
__device__ __align__(16) __half g_iS0[B * L * ISTR];
__device__ __align__(16) __half g_iS1[B * L * ISTR];
__device__ float g_fIn[B * L * FSTR];
__device__ float g_fF [B * L * FSTR];
__device__ float g_fS0[B * L * FSTR];
__device__ float g_fS1[B * L * FSTR];

struct GridS {
    int o00, o01, o10, o11;
    float w00, w01, w10, w11;   // border-pad weights (flows)
    float z00, z01, z10, z11;   // zeros-pad weights (images)
};

// EXACT reference-formula sequence (normalized coords, fmod wrap, unnormalize).
// Do NOT reassociate: the x-wrap is discontinuous and rounding-sensitive.
__device__ __forceinline__ GridS make_grid(float fx, float fyv, int w, int h)
{
    GridS g;
    float gx = ((float)w + 0.5f) * (2.0f / W) - 1.0f + fx;
    float gy = ((float)h + 0.5f) * (2.0f / H) - 1.0f + fyv;

    float r = fmodf(gx + 1.0f, 2.0f);
    if (r < 0.0f) r += 2.0f;
    float gxw = r - 1.0f;

    float x  = (gxw + 1.0f) * (0.5f * W) - 0.5f;
    float yy = (gy  + 1.0f) * (0.5f * H) - 0.5f;

    float x0f = floorf(x);
    float y0f = floorf(yy);
    float wx = x - x0f;
    float wy = yy - y0f;
    int x0 = (int)x0f, y0 = (int)y0f;
    int x1 = x0 + 1,   y1 = y0 + 1;

    int x0c = min(max(x0, 0), W - 1);
    int x1c = min(max(x1, 0), W - 1);
    int y0c = min(max(y0, 0), H - 1);
    int y1c = min(max(y1, 0), H - 1);

    g.w00 = (1.0f - wx) * (1.0f - wy);
    g.w01 = wx * (1.0f - wy);
    g.w10 = (1.0f - wx) * wy;
    g.w11 = wx * wy;

    g.o00 = y0c * W + x0c;
    g.o01 = y0c * W + x1c;
    g.o10 = y1c * W + x0c;
    g.o11 = y1c * W + x1c;

    bool vx0 = (x0 >= 0) && (x0 < W);
    bool vx1 = (x1 >= 0) && (x1 < W);
    bool vy0 = (y0 >= 0) && (y0 < H);
    bool vy1 = (y1 >= 0) && (y1 < H);
    g.z00 = (vy0 && vx0) ? g.w00 : 0.0f;
    g.z01 = (vy0 && vx1) ? g.w01 : 0.0f;
    g.z10 = (vy1 && vx0) ? g.w10 : 0.0f;
    g.z11 = (vy1 && vx1) ? g.w11 : 0.0f;
    return g;
}

__device__ __forceinline__ unsigned h2u(__half2 h) {
    unsigned u; *(__half2*)&u = h; return u;
}
__device__ __forceinline__ __half2 u2h(unsigned u) {
    return *(__half2*)&u;
}

// ---- images: planar fp32 -> interleaved fp16 --------------------------------
__global__ __launch_bounds__(256)
void img_pre_kernel(const float* __restrict__ src, __half* __restrict__ dst)
{
    __shared__ float sm[64 * 17];
    int tid = threadIdx.x;
    int pb = blockIdx.x * 64;
    size_t bt = blockIdx.y;
    const float* s = src + bt * ISTR;
    #pragma unroll
    for (int rr = 0; rr < 4; rr++) {
        int c = (tid >> 6) + rr * 4;
        int i = tid & 63;
        sm[i * 17 + c] = s[c * HW + pb + i];
    }
    __syncthreads();
    // 64 px * 16 ch = 1024 halves; each thread writes 4 consecutive halves (8B)
    __half* d = dst + bt * ISTR + (size_t)pb * 16;
    int hbase = tid * 4;
    int px = hbase >> 4, ch = hbase & 15;
    __half2 h0 = __floats2half2_rn(sm[px * 17 + ch],     sm[px * 17 + ch + 1]);
    __half2 h1 = __floats2half2_rn(sm[px * 17 + ch + 2], sm[px * 17 + ch + 3]);
    uint2 u; u.x = h2u(h0); u.y = h2u(h1);
    ((uint2*)d)[tid] = u;
}

// ---- flows: planar -> interleaved fp32 --------------------------------------
__global__ __launch_bounds__(256)
void flow_pre_kernel(const float* __restrict__ src, float* __restrict__ dst)
{
    int p = blockIdx.x * 256 + threadIdx.x;
    size_t bt = blockIdx.y;
    const float* s = src + bt * FSTR;
    ((float2*)(dst + bt * FSTR))[p] = make_float2(s[p], s[HW + p]);
}

// ---- t=0 image passthrough: planar input -> planar d_out --------------------
__global__ __launch_bounds__(256)
void t0_copy_kernel(const float* __restrict__ src, float* __restrict__ dst)
{
    int idx = blockIdx.x * 256 + threadIdx.x;          // gridDim.x = 256
    size_t off = (size_t)blockIdx.y * L * ISTR;        // b slice, t = 0
    ((float4*)(dst + off))[idx] = ((const float4*)(src + off))[idx];
}

// ---- fused pscan step, templated --------------------------------------------
// FMODE: 1 = flow everywhere, 2 = flow only for scratch region, 0 = no flow.
template<int S, int FMODE>
__global__ __launch_bounds__(256)
void step_kernel(const __half* __restrict__ iIn, const __half* iFr, __half* iFw,
                 const __half* __restrict__ iprev, __half* __restrict__ iscr,
                 float* __restrict__ out,
                 const float* __restrict__ fIn, const float* fFr, float* fFw,
                 const float* __restrict__ fprev, float* __restrict__ fscr)
{
    constexpr int Ls = L - S;
    constexpr bool LAST = (S == 16);
    __shared__ float sm[64 * 17];

    int tid = threadIdx.x;
    int chunk = tid & 3;
    int pl = tid >> 2;
    int pb = blockIdx.x * 64, p = pb + pl;         // gridDim.x = 256
    int y = blockIdx.y;                            // B * Ls
    int b = y / Ls, trel = y % Ls;
    int t = S + trel, j = trel;
    bool final_t = (trel < S);                     // uniform per block
    size_t bt  = (size_t)(b * L + t);
    size_t btj = (size_t)(b * L + j);

    float2 fc = ((const float2*)(fprev + bt * FSTR))[p];
    int w = p & (W - 1), h = p >> 7;
    GridS g = make_grid(fc.x, fc.y, w, h);

    size_t pix16 = (size_t)p * 16 + chunk * 4;

    // current value (fp16, 8B coalesced)
    uint2 cu = *(const uint2*)(iprev + bt * ISTR + pix16);
    float2 c01 = __half22float2(u2h(cu.x));
    float2 c23 = __half22float2(u2h(cu.y));
    float a0 = c01.x, a1 = c01.y, a2 = c23.x, a3 = c23.y;

    // gather: 4 taps, 8B each
    const __half* ibase = (j == 0) ? iIn : (j < S) ? iFr : iprev;
    const __half* srcp = ibase + btj * ISTR + chunk * 4;
    uint2 u00 = *(const uint2*)(srcp + (size_t)g.o00 * 16);
    uint2 u01 = *(const uint2*)(srcp + (size_t)g.o01 * 16);
    uint2 u10 = *(const uint2*)(srcp + (size_t)g.o10 * 16);
    uint2 u11 = *(const uint2*)(srcp + (size_t)g.o11 * 16);

    {
        float2 f0 = __half22float2(u2h(u00.x)), f1 = __half22float2(u2h(u00.y));
        a0 += g.z00 * f0.x; a1 += g.z00 * f0.y; a2 += g.z00 * f1.x; a3 += g.z00 * f1.y;
    }
    {
        float2 f0 = __half22float2(u2h(u01.x)), f1 = __half22float2(u2h(u01.y));
        a0 += g.z01 * f0.x; a1 += g.z01 * f0.y; a2 += g.z01 * f1.x; a3 += g.z01 * f1.y;
    }
    {
        float2 f0 = __half22float2(u2h(u10.x)), f1 = __half22float2(u2h(u10.y));
        a0 += g.z10 * f0.x; a1 += g.z10 * f0.y; a2 += g.z10 * f1.x; a3 += g.z10 * f1.y;
    }
    {
        float2 f0 = __half22float2(u2h(u11.x)), f1 = __half22float2(u2h(u11.y));
        a0 += g.z11 * f0.x; a1 += g.z11 * f0.y; a2 += g.z11 * f1.x; a3 += g.z11 * f1.y;
    }

    if (final_t) {
        if (!LAST) {   // re-readable fp16 finals copy
            __half2 h0 = __floats2half2_rn(a0, a1);
            __half2 h1 = __floats2half2_rn(a2, a3);
            uint2 su; su.x = h2u(h0); su.y = h2u(h1);
            *(uint2*)(iFw + bt * ISTR + pix16) = su;
        }
        // exact fp32 planar d_out via conflict-free smem bounce
        int cb = chunk * 4;
        sm[pl * 17 + cb + 0] = a0;
        sm[pl * 17 + cb + 1] = a1;
        sm[pl * 17 + cb + 2] = a2;
        sm[pl * 17 + cb + 3] = a3;
        __syncthreads();
        float* dst = out + bt * ISTR;
        #pragma unroll
        for (int rr = 0; rr < 4; rr++) {
            int c = (tid >> 6) + rr * 4;
            int i = tid & 63;
            dst[c * HW + pb + i] = sm[i * 17 + c];
        }
    } else {
        __half2 h0 = __floats2half2_rn(a0, a1);
        __half2 h1 = __floats2half2_rn(a2, a3);
        uint2 su; su.x = h2u(h0); su.y = h2u(h1);
        *(uint2*)(iscr + bt * ISTR + pix16) = su;
    }

    // ---- flow (fp32): chunk-0 lanes ----
    if (FMODE != 0 && chunk == 0) {
        bool doflow = (FMODE == 1) || !final_t;
        if (doflow) {
            const float* fbase = (j == 0) ? fIn : (j < S) ? fFr : fprev;
            const float2* fsrc = (const float2*)(fbase + btj * FSTR);
            float2 t00 = fsrc[g.o00], t01 = fsrc[g.o01];
            float2 t10 = fsrc[g.o10], t11 = fsrc[g.o11];
            float nx = fc.x + g.w00 * t00.x + g.w01 * t01.x + g.w10 * t10.x + g.w11 * t11.x;
            float ny = fc.y + g.w00 * t00.y + g.w01 * t01.y + g.w10 * t10.y + g.w11 * t11.y;
            float* fdst = final_t ? fFw : fscr;
            ((float2*)(fdst + bt * FSTR))[p] = make_float2(nx, ny);
        }
    }
}

extern "C" void kernel_launch(void* const* d_in, const int* in_sizes, int n_in,
                              void* d_out, int out_size)
{
    const float* flows  = (const float*)d_in[0];
    const float* images = (const float*)d_in[1];
    if (n_in >= 2 && in_sizes[0] > in_sizes[1]) {
        flows  = (const float*)d_in[1];
        images = (const float*)d_in[0];
    }
    float* out = (float*)d_out;

    __half *iIn, *iF, *iS0, *iS1;
    float *fIn, *fF, *fS0, *fS1;
    cudaGetSymbolAddress((void**)&iIn, g_iIn);
    cudaGetSymbolAddress((void**)&iF,  g_iF);
    cudaGetSymbolAddress((void**)&iS0, g_iS0);
    cudaGetSymbolAddress((void**)&iS1, g_iS1);
    cudaGetSymbolAddress((void**)&fIn, g_fIn);
    cudaGetSymbolAddress((void**)&fF,  g_fF);
    cudaGetSymbolAddress((void**)&fS0, g_fS0);
    cudaGetSymbolAddress((void**)&fS1, g_fS1);

    img_pre_kernel <<<dim3(256, B * L), 256>>>(images, iIn);
    flow_pre_kernel<<<dim3(64,  B * L), 256>>>(flows, fIn);
    t0_copy_kernel <<<dim3(256, B),     256>>>(images, out);

    step_kernel<1, 1><<<dim3(256, B * 31), 256>>>(iIn, iF, iF, iIn, iS0, out,
                                                  fIn, fF, fF, fIn, fS0);
    step_kernel<2, 1><<<dim3(256, B * 30), 256>>>(iIn, iF, iF, iS0, iS1, out,
                                                  fIn, fF, fF, fS0, fS1);
    step_kernel<4, 2><<<dim3(256, B * 28), 256>>>(iIn, iF, iF, iS1, iS0, out,
                                                  fIn, fF, fF, fS1, fS0);
    step_kernel<8, 2><<<dim3(256, B * 24), 256>>>(iIn, iF, iF, iS0, iS1, out,
                                                  fIn, fF, fF, fS0, fS1);
    step_kernel<16, 0><<<dim3(256, B * 16), 256>>>(iIn, iF, iF, iS1, iS0, out,
                                                   fIn, fF, fF, fS1, fS0);
}

// round 9
// speedup vs baseline: 1.7143x; 1.1125x over previous
#include <cuda_runtime.h>
#include <cuda_fp16.h>
#include <cstdint>

// flows:  [B=4, L=32, 2,  H=128, W=128] fp32 planar input (fp32 internally)
// images: [B=4, L=32, 16, H=128, W=128] fp32 planar in/out; internal state fp16
//         channel-interleaved [bt][hw][16].
// pscan steps s = 1,2,4,8,16, no-copy routing:
//   step s: t in [s,2s) FINAL -> planar fp32 d_out (+ fp16 iF unless last step)
//           t in [2s,L)       -> fp16 scratch ping-pong
//   reads j = t-s: j==0 -> iIn, 1<=j<s -> iF, j>=s -> prev scratch.
// 2 threads per pixel: each owns 8 channels (16B = one uint4 per tap).

constexpr int B  = 4;
constexpr int L  = 32;
constexpr int C  = 16;
constexpr int H  = 128;
constexpr int W  = 128;
constexpr int HW = H * W;
constexpr int FSTR = 2 * HW;
constexpr int ISTR = C * HW;

__device__ __align__(16) __half g_iIn[B * L * ISTR];
__device__ __align__(16) __half g_iF [B * L * ISTR];
__device__ __align__(16) __half g_iS0[B * L * ISTR];
__device__ __align__(16) __half g_iS1[B * L * ISTR];
__device__ float g_fIn[B * L * FSTR];
__device__ float g_fF [B * L * FSTR];
__device__ float g_fS0[B * L * FSTR];
__device__ float g_fS1[B * L * FSTR];

struct GridS {
    int o00, o01, o10, o11;
    float w00, w01, w10, w11;   // border-pad weights (flows)
    float z00, z01, z10, z11;   // zeros-pad weights (images)
};

// EXACT reference-formula sequence (normalized coords, fmod wrap, unnormalize).
// Do NOT reassociate: the x-wrap is discontinuous and rounding-sensitive.
__device__ __forceinline__ GridS make_grid(float fx, float fyv, int w, int h)
{
    GridS g;
    float gx = ((float)w + 0.5f) * (2.0f / W) - 1.0f + fx;
    float gy = ((float)h + 0.5f) * (2.0f / H) - 1.0f + fyv;

    float r = fmodf(gx + 1.0f, 2.0f);
    if (r < 0.0f) r += 2.0f;
    float gxw = r - 1.0f;

    float x  = (gxw + 1.0f) * (0.5f * W) - 0.5f;
    float yy = (gy  + 1.0f) * (0.5f * H) - 0.5f;

    float x0f = floorf(x);
    float y0f = floorf(yy);
    float wx = x - x0f;
    float wy = yy - y0f;
    int x0 = (int)x0f, y0 = (int)y0f;
    int x1 = x0 + 1,   y1 = y0 + 1;

    int x0c = min(max(x0, 0), W - 1);
    int x1c = min(max(x1, 0), W - 1);
    int y0c = min(max(y0, 0), H - 1);
    int y1c = min(max(y1, 0), H - 1);

    g.w00 = (1.0f - wx) * (1.0f - wy);
    g.w01 = wx * (1.0f - wy);
    g.w10 = (1.0f - wx) * wy;
    g.w11 = wx * wy;

    g.o00 = y0c * W + x0c;
    g.o01 = y0c * W + x1c;
    g.o10 = y1c * W + x0c;
    g.o11 = y1c * W + x1c;

    bool vx0 = (x0 >= 0) && (x0 < W);
    bool vx1 = (x1 >= 0) && (x1 < W);
    bool vy0 = (y0 >= 0) && (y0 < H);
    bool vy1 = (y1 >= 0) && (y1 < H);
    g.z00 = (vy0 && vx0) ? g.w00 : 0.0f;
    g.z01 = (vy0 && vx1) ? g.w01 : 0.0f;
    g.z10 = (vy1 && vx0) ? g.w10 : 0.0f;
    g.z11 = (vy1 && vx1) ? g.w11 : 0.0f;
    return g;
}

__device__ __forceinline__ unsigned h2u(__half2 h) {
    unsigned u; *(__half2*)&u = h; return u;
}
__device__ __forceinline__ __half2 u2h(unsigned u) {
    return *(__half2*)&u;
}

__device__ __forceinline__ void acc8(float* a, uint4 u, float z)
{
    float2 f;
    f = __half22float2(u2h(u.x)); a[0] += z * f.x; a[1] += z * f.y;
    f = __half22float2(u2h(u.y)); a[2] += z * f.x; a[3] += z * f.y;
    f = __half22float2(u2h(u.z)); a[4] += z * f.x; a[5] += z * f.y;
    f = __half22float2(u2h(u.w)); a[6] += z * f.x; a[7] += z * f.y;
}

// ---- images: planar fp32 -> interleaved fp16 --------------------------------
__global__ __launch_bounds__(256)
void img_pre_kernel(const float* __restrict__ src, __half* __restrict__ dst)
{
    __shared__ float sm[64 * 17];
    int tid = threadIdx.x;
    int pb = blockIdx.x * 64;
    size_t bt = blockIdx.y;
    const float* s = src + bt * ISTR;
    #pragma unroll
    for (int rr = 0; rr < 4; rr++) {
        int c = (tid >> 6) + rr * 4;
        int i = tid & 63;
        sm[i * 17 + c] = s[c * HW + pb + i];
    }
    __syncthreads();
    __half* d = dst + bt * ISTR + (size_t)pb * 16;
    int hbase = tid * 4;
    int px = hbase >> 4, ch = hbase & 15;
    __half2 h0 = __floats2half2_rn(sm[px * 17 + ch],     sm[px * 17 + ch + 1]);
    __half2 h1 = __floats2half2_rn(sm[px * 17 + ch + 2], sm[px * 17 + ch + 3]);
    uint2 u; u.x = h2u(h0); u.y = h2u(h1);
    ((uint2*)d)[tid] = u;
}

// ---- flows: planar -> interleaved fp32 --------------------------------------
__global__ __launch_bounds__(256)
void flow_pre_kernel(const float* __restrict__ src, float* __restrict__ dst)
{
    int p = blockIdx.x * 256 + threadIdx.x;
    size_t bt = blockIdx.y;
    const float* s = src + bt * FSTR;
    ((float2*)(dst + bt * FSTR))[p] = make_float2(s[p], s[HW + p]);
}

// ---- t=0 image passthrough: planar input -> planar d_out --------------------
__global__ __launch_bounds__(256)
void t0_copy_kernel(const float* __restrict__ src, float* __restrict__ dst)
{
    int idx = blockIdx.x * 256 + threadIdx.x;          // gridDim.x = 256
    size_t off = (size_t)blockIdx.y * L * ISTR;        // b slice, t = 0
    ((float4*)(dst + off))[idx] = ((const float4*)(src + off))[idx];
}

// ---- fused pscan step: 2 threads/pixel --------------------------------------
// FMODE: 1 = flow everywhere, 2 = flow only for scratch region, 0 = no flow.
template<int S, int FMODE>
__global__ __launch_bounds__(256)
void step_kernel(const __half* __restrict__ iIn, const __half* iFr, __half* iFw,
                 const __half* __restrict__ iprev, __half* __restrict__ iscr,
                 float* __restrict__ out,
                 const float* __restrict__ fIn, const float* fFr, float* fFw,
                 const float* __restrict__ fprev, float* __restrict__ fscr)
{
    constexpr int Ls = L - S;
    constexpr bool LAST = (S == 16);
    __shared__ float sm[128 * 17];

    int tid = threadIdx.x;
    int half_ = tid & 1;                // which 8-channel half
    int pl = tid >> 1;                  // 128 pixels per block
    int pb = blockIdx.x * 128, p = pb + pl;   // gridDim.x = 128
    int y = blockIdx.y;                 // B * Ls
    int b = y / Ls, trel = y % Ls;
    int t = S + trel, j = trel;
    bool final_t = (trel < S);          // uniform per block
    size_t bt  = (size_t)(b * L + t);
    size_t btj = (size_t)(b * L + j);

    float2 fc = ((const float2*)(fprev + bt * FSTR))[p];
    int w = p & (W - 1), h = p >> 7;
    GridS g = make_grid(fc.x, fc.y, w, h);

    size_t pixoff = (size_t)p * 16 + half_ * 8;

    // current value (fp16, 16B coalesced)
    uint4 cu = *(const uint4*)(iprev + bt * ISTR + pixoff);
    float a[8];
    {
        float2 f;
        f = __half22float2(u2h(cu.x)); a[0] = f.x; a[1] = f.y;
        f = __half22float2(u2h(cu.y)); a[2] = f.x; a[3] = f.y;
        f = __half22float2(u2h(cu.z)); a[4] = f.x; a[5] = f.y;
        f = __half22float2(u2h(cu.w)); a[6] = f.x; a[7] = f.y;
    }

    // gather: 4 taps, 16B each
    const __half* ibase = (j == 0) ? iIn : (j < S) ? iFr : iprev;
    const __half* srcp = ibase + btj * ISTR + half_ * 8;
    uint4 u00 = *(const uint4*)(srcp + (size_t)g.o00 * 16);
    uint4 u01 = *(const uint4*)(srcp + (size_t)g.o01 * 16);
    uint4 u10 = *(const uint4*)(srcp + (size_t)g.o10 * 16);
    uint4 u11 = *(const uint4*)(srcp + (size_t)g.o11 * 16);
    acc8(a, u00, g.z00);
    acc8(a, u01, g.z01);
    acc8(a, u10, g.z10);
    acc8(a, u11, g.z11);

    if (final_t) {
        if (!LAST) {   // re-readable fp16 finals copy
            uint4 su;
            su.x = h2u(__floats2half2_rn(a[0], a[1]));
            su.y = h2u(__floats2half2_rn(a[2], a[3]));
            su.z = h2u(__floats2half2_rn(a[4], a[5]));
            su.w = h2u(__floats2half2_rn(a[6], a[7]));
            *(uint4*)(iFw + bt * ISTR + pixoff) = su;
        }
        // exact fp32 planar d_out via conflict-free smem bounce
        int cb = half_ * 8;
        #pragma unroll
        for (int k = 0; k < 8; k++) sm[pl * 17 + cb + k] = a[k];
        __syncthreads();
        float* dst = out + bt * ISTR;
        #pragma unroll
        for (int rr = 0; rr < 8; rr++) {
            int c = (tid >> 7) + rr * 2;
            int i = tid & 127;
            dst[c * HW + pb + i] = sm[i * 17 + c];
        }
    } else {
        uint4 su;
        su.x = h2u(__floats2half2_rn(a[0], a[1]));
        su.y = h2u(__floats2half2_rn(a[2], a[3]));
        su.z = h2u(__floats2half2_rn(a[4], a[5]));
        su.w = h2u(__floats2half2_rn(a[6], a[7]));
        *(uint4*)(iscr + bt * ISTR + pixoff) = su;
    }

    // ---- flow (fp32): one lane per pixel ----
    if (FMODE != 0 && half_ == 0) {
        bool doflow = (FMODE == 1) || !final_t;
        if (doflow) {
            const float* fbase = (j == 0) ? fIn : (j < S) ? fFr : fprev;
            const float2* fsrc = (const float2*)(fbase + btj * FSTR);
            float2 t00 = fsrc[g.o00], t01 = fsrc[g.o01];
            float2 t10 = fsrc[g.o10], t11 = fsrc[g.o11];
            float nx = fc.x + g.w00 * t00.x + g.w01 * t01.x + g.w10 * t10.x + g.w11 * t11.x;
            float ny = fc.y + g.w00 * t00.y + g.w01 * t01.y + g.w10 * t10.y + g.w11 * t11.y;
            float* fdst = final_t ? fFw : fscr;
            ((float2*)(fdst + bt * FSTR))[p] = make_float2(nx, ny);
        }
    }
}

extern "C" void kernel_launch(void* const* d_in, const int* in_sizes, int n_in,
                              void* d_out, int out_size)
{
    const float* flows  = (const float*)d_in[0];
    const float* images = (const float*)d_in[1];
    if (n_in >= 2 && in_sizes[0] > in_sizes[1]) {
        flows  = (const float*)d_in[1];
        images = (const float*)d_in[0];
    }
    float* out = (float*)d_out;

    __half *iIn, *iF, *iS0, *iS1;
    float *fIn, *fF, *fS0, *fS1;
    cudaGetSymbolAddress((void**)&iIn, g_iIn);
    cudaGetSymbolAddress((void**)&iF,  g_iF);
    cudaGetSymbolAddress((void**)&iS0, g_iS0);
    cudaGetSymbolAddress((void**)&iS1, g_iS1);
    cudaGetSymbolAddress((void**)&fIn, g_fIn);
    cudaGetSymbolAddress((void**)&fF,  g_fF);
    cudaGetSymbolAddress((void**)&fS0, g_fS0);
    cudaGetSymbolAddress((void**)&fS1, g_fS1);

    img_pre_kernel <<<dim3(256, B * L), 256>>>(images, iIn);
    flow_pre_kernel<<<dim3(64,  B * L), 256>>>(flows, fIn);
    t0_copy_kernel <<<dim3(256, B),     256>>>(images, out);

    step_kernel<1, 1><<<dim3(128, B * 31), 256>>>(iIn, iF, iF, iIn, iS0, out,
                                                  fIn, fF, fF, fIn, fS0);
    step_kernel<2, 1><<<dim3(128, B * 30), 256>>>(iIn, iF, iF, iS0, iS1, out,
                                                  fIn, fF, fF, fS0, fS1);
    step_kernel<4, 2><<<dim3(128, B * 28), 256>>>(iIn, iF, iF, iS1, iS0, out,
                                                  fIn, fF, fF, fS1, fS0);
    step_kernel<8, 2><<<dim3(128, B * 24), 256>>>(iIn, iF, iF, iS0, iS1, out,
                                                  fIn, fF, fF, fS0, fS1);
    step_kernel<16, 0><<<dim3(128, B * 16), 256>>>(iIn, iF, iF, iS1, iS0, out,
                                                   fIn, fF, fF, fS1, fS0);
}

// round 10
// speedup vs baseline: 1.7587x; 1.0259x over previous
#include <cuda_runtime.h>
#include <cuda_fp16.h>
#include <cstdint>

// flows:  [B=4, L=32, 2,  H=128, W=128] fp32 planar input (fp32 internally)
// images: [B=4, L=32, 16, H=128, W=128] fp32 planar in/out; internal state fp16
//         channel-interleaved [bt][hw][16].
// pscan steps s = 1,2,4,8,16, no-copy routing:
//   step s: t in [s,2s) FINAL -> planar fp32 d_out (+ fp16 iF unless last step)
//           t in [2s,L)       -> fp16 scratch ping-pong
//   image reads j = t-s: j==0 -> iIn, 1<=j<s -> iF, j>=s -> prev scratch.
// Flow: final-region flow outputs are provably never read (the only consumer
// chain is later final-region flow, terminated by flowless s=16), so flow is
// computed ONLY for scratch-region slices; sources are always fprev (j>=s).

constexpr int B  = 4;
constexpr int L  = 32;
constexpr int C  = 16;
constexpr int H  = 128;
constexpr int W  = 128;
constexpr int HW = H * W;
constexpr int FSTR = 2 * HW;
constexpr int ISTR = C * HW;

__device__ __align__(16) __half g_iIn[B * L * ISTR];
__device__ __align__(16) __half g_iF [B * L * ISTR];
__device__ __align__(16) __half g_iS0[B * L * ISTR];
__device__ __align__(16) __half g_iS1[B * L * ISTR];
__device__ float g_fIn[B * L * FSTR];
__device__ float g_fS0[B * L * FSTR];
__device__ float g_fS1[B * L * FSTR];

struct GridS {
    int o00, o01, o10, o11;
    float w00, w01, w10, w11;   // border-pad weights (flows)
    float z00, z01, z10, z11;   // zeros-pad weights (images)
};

// Reference-exact grid computation. The x-wrap uses conditional +/-2 steps
// that are bit-identical to fmodf(v,2)+fixup for v in [-4,4) (each +/-2 is
// exact there; -0.0 and boundary cases coincide with JAX remainder), with a
// fmodf fallback for out-of-range values.
__device__ __forceinline__ GridS make_grid(float fx, float fyv, int w, int h)
{
    GridS g;
    float gx = ((float)w + 0.5f) * (2.0f / W) - 1.0f + fx;
    float gy = ((float)h + 0.5f) * (2.0f / H) - 1.0f + fyv;

    float v = gx + 1.0f;
    if (v >= 4.0f || v < -4.0f) {
        v = fmodf(v, 2.0f);          // (-2,2), trunc-rem like reference
    }
    if (v >= 2.0f) v -= 2.0f;
    if (v >= 2.0f) v -= 2.0f;
    if (v < 0.0f)  v += 2.0f;
    if (v < 0.0f)  v += 2.0f;
    float gxw = v - 1.0f;

    float x  = (gxw + 1.0f) * (0.5f * W) - 0.5f;
    float yy = (gy  + 1.0f) * (0.5f * H) - 0.5f;

    float x0f = floorf(x);
    float y0f = floorf(yy);
    float wx = x - x0f;
    float wy = yy - y0f;
    int x0 = (int)x0f, y0 = (int)y0f;
    int x1 = x0 + 1,   y1 = y0 + 1;

    int x0c = min(max(x0, 0), W - 1);
    int x1c = min(max(x1, 0), W - 1);
    int y0c = min(max(y0, 0), H - 1);
    int y1c = min(max(y1, 0), H - 1);

    g.w00 = (1.0f - wx) * (1.0f - wy);
    g.w01 = wx * (1.0f - wy);
    g.w10 = (1.0f - wx) * wy;
    g.w11 = wx * wy;

    g.o00 = y0c * W + x0c;
    g.o01 = y0c * W + x1c;
    g.o10 = y1c * W + x0c;
    g.o11 = y1c * W + x1c;

    bool vx0 = (x0 >= 0) && (x0 < W);
    bool vx1 = (x1 >= 0) && (x1 < W);
    bool vy0 = (y0 >= 0) && (y0 < H);
    bool vy1 = (y1 >= 0) && (y1 < H);
    g.z00 = (vy0 && vx0) ? g.w00 : 0.0f;
    g.z01 = (vy0 && vx1) ? g.w01 : 0.0f;
    g.z10 = (vy1 && vx0) ? g.w10 : 0.0f;
    g.z11 = (vy1 && vx1) ? g.w11 : 0.0f;
    return g;
}

__device__ __forceinline__ unsigned h2u(__half2 h) {
    unsigned u; *(__half2*)&u = h; return u;
}
__device__ __forceinline__ __half2 u2h(unsigned u) {
    return *(__half2*)&u;
}

__device__ __forceinline__ void acc8(float* a, uint4 u, float z)
{
    float2 f;
    f = __half22float2(u2h(u.x)); a[0] += z * f.x; a[1] += z * f.y;
    f = __half22float2(u2h(u.y)); a[2] += z * f.x; a[3] += z * f.y;
    f = __half22float2(u2h(u.z)); a[4] += z * f.x; a[5] += z * f.y;
    f = __half22float2(u2h(u.w)); a[6] += z * f.x; a[7] += z * f.y;
}

// ---- images: planar fp32 -> interleaved fp16 (+ t=0 planar passthrough) -----
__global__ __launch_bounds__(256)
void img_pre_kernel(const float* __restrict__ src, __half* __restrict__ dst,
                    float* __restrict__ out)
{
    __shared__ float sm[64 * 17];
    int tid = threadIdx.x;
    int pb = blockIdx.x * 64;
    size_t bt = blockIdx.y;
    bool is_t0 = ((bt & (L - 1)) == 0);
    const float* s = src + bt * ISTR;
    float* o = out + bt * ISTR;
    #pragma unroll
    for (int rr = 0; rr < 4; rr++) {
        int c = (tid >> 6) + rr * 4;
        int i = tid & 63;
        float v = s[c * HW + pb + i];
        sm[i * 17 + c] = v;
        if (is_t0) o[c * HW + pb + i] = v;   // fused t=0 passthrough
    }
    __syncthreads();
    __half* d = dst + bt * ISTR + (size_t)pb * 16;
    int hbase = tid * 4;
    int px = hbase >> 4, ch = hbase & 15;
    __half2 h0 = __floats2half2_rn(sm[px * 17 + ch],     sm[px * 17 + ch + 1]);
    __half2 h1 = __floats2half2_rn(sm[px * 17 + ch + 2], sm[px * 17 + ch + 3]);
    uint2 u; u.x = h2u(h0); u.y = h2u(h1);
    ((uint2*)d)[tid] = u;
}

// ---- flows: planar -> interleaved fp32 --------------------------------------
__global__ __launch_bounds__(256)
void flow_pre_kernel(const float* __restrict__ src, float* __restrict__ dst)
{
    int p = blockIdx.x * 256 + threadIdx.x;
    size_t bt = blockIdx.y;
    const float* s = src + bt * FSTR;
    ((float2*)(dst + bt * FSTR))[p] = make_float2(s[p], s[HW + p]);
}

// ---- fused pscan step: 2 threads/pixel --------------------------------------
// DOFLOW: 1 = flow for scratch-region slices, 0 = no flow at all.
template<int S, int DOFLOW>
__global__ __launch_bounds__(256)
void step_kernel(const __half* __restrict__ iIn, const __half* iFr, __half* iFw,
                 const __half* __restrict__ iprev, __half* __restrict__ iscr,
                 float* __restrict__ out,
                 const float* __restrict__ fprev, float* __restrict__ fscr)
{
    constexpr int Ls = L - S;
    constexpr bool LAST = (S == 16);
    __shared__ float sm[128 * 17];

    int tid = threadIdx.x;
    int half_ = tid & 1;                // which 8-channel half
    int pl = tid >> 1;                  // 128 pixels per block
    int pb = blockIdx.x * 128, p = pb + pl;   // gridDim.x = 128
    int y = blockIdx.y;                 // B * Ls
    int b = y / Ls, trel = y % Ls;
    int t = S + trel, j = trel;
    bool final_t = (trel < S);          // uniform per block
    size_t bt  = (size_t)(b * L + t);
    size_t btj = (size_t)(b * L + j);

    float2 fc = ((const float2*)(fprev + bt * FSTR))[p];
    int w = p & (W - 1), h = p >> 7;
    GridS g = make_grid(fc.x, fc.y, w, h);

    size_t pixoff = (size_t)p * 16 + half_ * 8;

    // current value (fp16, 16B coalesced)
    uint4 cu = *(const uint4*)(iprev + bt * ISTR + pixoff);
    float a[8];
    {
        float2 f;
        f = __half22float2(u2h(cu.x)); a[0] = f.x; a[1] = f.y;
        f = __half22float2(u2h(cu.y)); a[2] = f.x; a[3] = f.y;
        f = __half22float2(u2h(cu.z)); a[4] = f.x; a[5] = f.y;
        f = __half22float2(u2h(cu.w)); a[6] = f.x; a[7] = f.y;
    }

    // gather: 4 taps, 16B each
    const __half* ibase = (j == 0) ? iIn : (j < S) ? iFr : iprev;
    const __half* srcp = ibase + btj * ISTR + half_ * 8;
    uint4 u00 = *(const uint4*)(srcp + (size_t)g.o00 * 16);
    uint4 u01 = *(const uint4*)(srcp + (size_t)g.o01 * 16);
    uint4 u10 = *(const uint4*)(srcp + (size_t)g.o10 * 16);
    uint4 u11 = *(const uint4*)(srcp + (size_t)g.o11 * 16);
    acc8(a, u00, g.z00);
    acc8(a, u01, g.z01);
    acc8(a, u10, g.z10);
    acc8(a, u11, g.z11);

    if (final_t) {
        if (!LAST) {   // re-readable fp16 finals copy
            uint4 su;
            su.x = h2u(__floats2half2_rn(a[0], a[1]));
            su.y = h2u(__floats2half2_rn(a[2], a[3]));
            su.z = h2u(__floats2half2_rn(a[4], a[5]));
            su.w = h2u(__floats2half2_rn(a[6], a[7]));
            *(uint4*)(iFw + bt * ISTR + pixoff) = su;
        }
        // exact fp32 planar d_out via conflict-free smem bounce
        int cb = half_ * 8;
        #pragma unroll
        for (int k = 0; k < 8; k++) sm[pl * 17 + cb + k] = a[k];
        __syncthreads();
        float* dst = out + bt * ISTR;
        #pragma unroll
        for (int rr = 0; rr < 8; rr++) {
            int c = (tid >> 7) + rr * 2;
            int i = tid & 127;
            dst[c * HW + pb + i] = sm[i * 17 + c];
        }
    } else {
        uint4 su;
        su.x = h2u(__floats2half2_rn(a[0], a[1]));
        su.y = h2u(__floats2half2_rn(a[2], a[3]));
        su.z = h2u(__floats2half2_rn(a[4], a[5]));
        su.w = h2u(__floats2half2_rn(a[6], a[7]));
        *(uint4*)(iscr + bt * ISTR + pixoff) = su;
    }

    // ---- flow (fp32): scratch-region slices only, one lane per pixel ----
    // (final-region flow is provably dead; sources always fprev since j>=S)
    if (DOFLOW && half_ == 0 && !final_t) {
        const float2* fsrc = (const float2*)(fprev + btj * FSTR);
        float2 t00 = fsrc[g.o00], t01 = fsrc[g.o01];
        float2 t10 = fsrc[g.o10], t11 = fsrc[g.o11];
        float nx = fc.x + g.w00 * t00.x + g.w01 * t01.x + g.w10 * t10.x + g.w11 * t11.x;
        float ny = fc.y + g.w00 * t00.y + g.w01 * t01.y + g.w10 * t10.y + g.w11 * t11.y;
        ((float2*)(fscr + bt * FSTR))[p] = make_float2(nx, ny);
    }
}

extern "C" void kernel_launch(void* const* d_in, const int* in_sizes, int n_in,
                              void* d_out, int out_size)
{
    const float* flows  = (const float*)d_in[0];
    const float* images = (const float*)d_in[1];
    if (n_in >= 2 && in_sizes[0] > in_sizes[1]) {
        flows  = (const float*)d_in[1];
        images = (const float*)d_in[0];
    }
    float* out = (float*)d_out;

    __half *iIn, *iF, *iS0, *iS1;
    float *fIn, *fS0, *fS1;
    cudaGetSymbolAddress((void**)&iIn, g_iIn);
    cudaGetSymbolAddress((void**)&iF,  g_iF);
    cudaGetSymbolAddress((void**)&iS0, g_iS0);
    cudaGetSymbolAddress((void**)&iS1, g_iS1);
    cudaGetSymbolAddress((void**)&fIn, g_fIn);
    cudaGetSymbolAddress((void**)&fS0, g_fS0);
    cudaGetSymbolAddress((void**)&fS1, g_fS1);

    img_pre_kernel <<<dim3(256, B * L), 256>>>(images, iIn, out);
    flow_pre_kernel<<<dim3(64,  B * L), 256>>>(flows, fIn);

    step_kernel<1, 1><<<dim3(128, B * 31), 256>>>(iIn, iF, iF, iIn, iS0, out,
                                                  fIn, fS0);
    step_kernel<2, 1><<<dim3(128, B * 30), 256>>>(iIn, iF, iF, iS0, iS1, out,
                                                  fS0, fS1);
    step_kernel<4, 1><<<dim3(128, B * 28), 256>>>(iIn, iF, iF, iS1, iS0, out,
                                                  fS1, fS0);
    step_kernel<8, 1><<<dim3(128, B * 24), 256>>>(iIn, iF, iF, iS0, iS1, out,
                                                  fS0, fS1);
    step_kernel<16, 0><<<dim3(128, B * 16), 256>>>(iIn, iF, iF, iS1, iS0, out,
                                                   fS1, fS0);
}